// round 5
// baseline (speedup 1.0000x reference)
#include <cuda_runtime.h>
#include <math.h>
#include <limits.h>

// CRF loss: out[b] = logZ(b) - label_score(b).  B=512, S=512, L=128.
//
// Scaled linear-space forward recursion, TWO batches per block.
// Block = 256 threads = 8 warps; lane layout: j = w*16 + (lane&15),
// h = lane>>4 (half of the i-range). Thread (j,h) holds E rows
// [64h,64h+64) of column j as 32 f32x2 regs. Each step computes the
// partial GEMV for BOTH batches against the same E registers (2x
// independent FMA chains), combines halves with one shfl_xor(16) per
// batch, scales by r=rcp(U[0]) and exp(x_t) (off the FFMA chain), and
// double-buffers U in skewed shared (ONE barrier/step). Batches are
// length-sorted and paired adjacently; 256 blocks x 2 CTA/SM = 1 wave.

#define LDIM 128

__device__ int d_perm[1024];

__device__ __forceinline__ unsigned long long pack_f32x2(float lo, float hi) {
    unsigned long long r;
    asm("mov.b64 %0, {%1, %2};" : "=l"(r) : "f"(lo), "f"(hi));
    return r;
}
__device__ __forceinline__ void unpack_f32x2(unsigned long long v, float& lo, float& hi) {
    asm("mov.b64 {%0, %1}, %2;" : "=f"(lo), "=f"(hi) : "l"(v));
}
__device__ __forceinline__ unsigned long long fma_f32x2(unsigned long long a,
                                                        unsigned long long b,
                                                        unsigned long long c) {
    unsigned long long d;
    asm("fma.rn.f32x2 %0, %1, %2, %3;" : "=l"(d) : "l"(a), "l"(b), "l"(c));
    return d;
}
__device__ __forceinline__ unsigned long long add_f32x2(unsigned long long a,
                                                        unsigned long long b) {
    unsigned long long d;
    asm("add.rn.f32x2 %0, %1, %2;" : "=l"(d) : "l"(a), "l"(b));
    return d;
}
__device__ __forceinline__ float rcp_approx(float x) {
    float r;
    asm("rcp.approx.ftz.f32 %0, %1;" : "=f"(r) : "f"(x));
    return r;
}

// ------------- longest-first permutation (bitonic, 1 block) ---------------
__global__ void sort_len_kernel(const int* __restrict__ length, int B, int S)
{
    __shared__ int key[1024];
    __shared__ int val[1024];
    const int t = threadIdx.x;

    int k = INT_MAX;
    if (t < B) {
        int L = length[t];
        L = L < 1 ? 1 : (L > S ? S : L);
        k = -L;               // longest first
    }
    key[t] = k;
    val[t] = t;
    __syncthreads();

    for (int kk = 2; kk <= 1024; kk <<= 1) {
        for (int s = kk >> 1; s > 0; s >>= 1) {
            int p = t ^ s;
            if (p > t) {
                bool up = ((t & kk) == 0);
                int kt = key[t], kp = key[p];
                if ((kt > kp) == up) {
                    key[t] = kp; key[p] = kt;
                    int vt = val[t]; val[t] = val[p]; val[p] = vt;
                }
            }
            __syncthreads();
        }
    }
    if (t < B) d_perm[t] = val[t];
}

// ------------------------------ main kernel --------------------------------
__global__ __launch_bounds__(256, 2)
void crf_forward_kernel(const float* __restrict__ input,
                        const int*   __restrict__ label,
                        const int*   __restrict__ length,
                        const float* __restrict__ trans,
                        float* __restrict__ out,
                        int S, int B)
{
    // skew: U[i] at float index i + 4*(i>>6)  (max 131 < 136; 136*4%16==0)
    __shared__ __align__(16) float u_sh[2][2][136];   // [buf][g][state]
    __shared__ float wred[2][8];
    __shared__ float s_x00[2];
    __shared__ float s_ls[2];

    const int tid  = threadIdx.x;
    const int w    = tid >> 5;
    const int l    = tid & 31;
    const int h    = l >> 4;             // half of i-range
    const int j    = w * 16 + (l & 15);  // state column 0..127

    const int bid = blockIdx.x;
    const int b0  = d_perm[2 * bid];
    const int b1  = d_perm[(2 * bid + 1 < B) ? (2 * bid + 1) : (2 * bid)];

    int len0 = length[b0]; len0 = len0 < 1 ? 1 : (len0 > S ? S : len0);
    int len1 = length[b1]; len1 = len1 < 1 ? 1 : (len1 > S ? S : len1);
    const int maxlen = len0 > len1 ? len0 : len1;

    const float* xb0 = input + (size_t)b0 * S * LDIM;
    const float* xb1 = input + (size_t)b1 * S * LDIM;

    // ---------------- label scores (both batches) ----------------------
    for (int g = 0; g < 2; g++) {
        const float* xb = g ? xb1 : xb0;
        const int* labb = label + (size_t)(g ? b1 : b0) * S;
        const int  len  = g ? len1 : len0;
        float ls = 0.f;
        for (int t = tid; t < len; t += 256) {
            int lab = labb[t];
            ls += xb[(size_t)t * LDIM + lab];
            if (t + 1 < len) ls += trans[lab * LDIM + labb[t + 1]];
        }
        #pragma unroll
        for (int o = 16; o > 0; o >>= 1)
            ls += __shfl_xor_sync(0xffffffffu, ls, o);
        if (l == 0) wred[g][w] = ls;
    }
    __syncthreads();
    if (tid < 2) {
        float acc = 0.f;
        #pragma unroll
        for (int i = 0; i < 8; i++) acc += wred[tid][i];
        s_ls[tid] = acc;
    }

    // -------- E rows [64h, 64h+64) of column j: 32 f32x2 regs ----------
    unsigned long long E2[32];
    #pragma unroll
    for (int k = 0; k < 32; k++) {
        int i0 = 64 * h + 2 * k;
        float lo = __expf(trans[(i0)     * LDIM + j]);
        float hi = __expf(trans[(i0 + 1) * LDIM + j]);
        E2[k] = pack_f32x2(lo, hi);
    }

    // ---------------- init U, prefetch pipeline -------------------------
    const int widx = j + 4 * (j >> 6);           // skewed write index
    float x0g0 = xb0[j];
    float x0g1 = xb1[j];
    if (tid == 0) { s_x00[0] = x0g0; }
    if (tid == 1) { s_x00[1] = xb1[1]; }         // careful: need xb1[0]!
    // (tid==1 has j==1; fix: do both from tid 0)
    __syncthreads();
    if (tid == 0) { s_x00[1] = xb1[0]; }
    __syncthreads();
    const float x000 = s_x00[0];
    const float x001 = s_x00[1];

    float U0 = __expf(x0g0 - x000);
    float U1 = __expf(x0g1 - x001);
    if (h == 0) u_sh[0][0][widx] = U0;
    else        u_sh[0][1][widx] = U1;

    // x prefetch, 2 steps deep, clamped incrementing pointers
    const float* xend0 = xb0 + (size_t)(len0 - 1) * LDIM + j;
    const float* xend1 = xb1 + (size_t)(len1 - 1) * LDIM + j;
    const float* xp0 = xb0 + j + LDIM;  if (xp0 > xend0) xp0 = xend0;
    const float* xp1 = xb1 + j + LDIM;  if (xp1 > xend1) xp1 = xend1;
    float xA0 = *xp0, xA1 = *xp1;                 // x for t=1
    xp0 += LDIM; if (xp0 > xend0) xp0 = xend0;
    xp1 += LDIM; if (xp1 > xend1) xp1 = xend1;
    float xB0 = *xp0, xB1 = *xp1;                 // x for t=2

    float alog0 = 0.f, alog1 = 0.f;               // tid 0 only
    __syncthreads();

    // ---------------- forward recursion: t = 1 .. maxlen-1 --------------
    int cur = 0;
    for (int t = 1; t < maxlen; t++) {
        const int nxt = cur ^ 1;
        const float r0 = rcp_approx(u_sh[cur][0][0]);
        const float r1 = rcp_approx(u_sh[cur][1][0]);
        const float ex0 = __expf(xA0);
        const float ex1 = __expf(xA1);

        // rotate prefetch (x for t+2)
        xA0 = xB0; xA1 = xB1;
        xp0 += LDIM; if (xp0 > xend0) xp0 = xend0;
        xp1 += LDIM; if (xp1 > xend1) xp1 = xend1;
        xB0 = *xp0; xB1 = *xp1;

        // partial GEMVs for both batches over this thread's 64 rows
        const ulonglong2* uu0 =
            (const ulonglong2*)(&u_sh[cur][0][0] + 68 * h);
        const ulonglong2* uu1 =
            (const ulonglong2*)(&u_sh[cur][1][0] + 68 * h);
        unsigned long long a0 = 0ull, a1 = 0ull, a2 = 0ull, a3 = 0ull;
        unsigned long long c0 = 0ull, c1 = 0ull, c2 = 0ull, c3 = 0ull;
        #pragma unroll
        for (int k = 0; k < 16; k += 2) {
            ulonglong2 ua = uu0[k];
            ulonglong2 ub = uu0[k + 1];
            ulonglong2 va = uu1[k];
            ulonglong2 vb = uu1[k + 1];
            a0 = fma_f32x2(ua.x, E2[2 * k + 0], a0);
            a1 = fma_f32x2(ua.y, E2[2 * k + 1], a1);
            a2 = fma_f32x2(ub.x, E2[2 * k + 2], a2);
            a3 = fma_f32x2(ub.y, E2[2 * k + 3], a3);
            c0 = fma_f32x2(va.x, E2[2 * k + 0], c0);
            c1 = fma_f32x2(va.y, E2[2 * k + 1], c1);
            c2 = fma_f32x2(vb.x, E2[2 * k + 2], c2);
            c3 = fma_f32x2(vb.y, E2[2 * k + 3], c3);
        }
        unsigned long long sa = add_f32x2(add_f32x2(a0, a1), add_f32x2(a2, a3));
        unsigned long long sc = add_f32x2(add_f32x2(c0, c1), add_f32x2(c2, c3));
        float sa_lo, sa_hi, sc_lo, sc_hi;
        unpack_f32x2(sa, sa_lo, sa_hi);
        unpack_f32x2(sc, sc_lo, sc_hi);
        float s0 = sa_lo + sa_hi;
        float s1 = sc_lo + sc_hi;

        // combine halves (lane bit 4)
        s0 += __shfl_xor_sync(0xffffffffu, s0, 16);
        s1 += __shfl_xor_sync(0xffffffffu, s1, 16);

        // scale + freeze after each batch's own length
        float n0 = s0 * (r0 * ex0);
        float n1 = s1 * (r1 * ex1);
        U0 = (t < len0) ? n0 : U0;
        U1 = (t < len1) ? n1 : U1;
        if (h == 0) u_sh[nxt][0][widx] = U0;
        else        u_sh[nxt][1][widx] = U1;
        if (tid == 0) {
            alog0 += (t < len0) ? __logf(r0) : 0.f;
            alog1 += (t < len1) ? __logf(r1) : 0.f;
        }
        cur = nxt;
        __syncthreads();
    }

    // ---------------- outputs ------------------------------------------
    float es0 = (h == 0) ? U0 : 0.f;
    float es1 = (h == 0) ? U1 : 0.f;
    #pragma unroll
    for (int o = 16; o > 0; o >>= 1) {
        es0 += __shfl_xor_sync(0xffffffffu, es0, o);
        es1 += __shfl_xor_sync(0xffffffffu, es1, o);
    }
    if (l == 0) { wred[0][w] = es0; wred[1][w] = es1; }
    __syncthreads();
    if (tid == 0) {
        float ss0 = 0.f, ss1 = 0.f;
        #pragma unroll
        for (int i = 0; i < 8; i++) { ss0 += wred[0][i]; ss1 += wred[1][i]; }
        out[b0] = x000 - alog0 + logf(ss0) - s_ls[0];
        out[b1] = x001 - alog1 + logf(ss1) - s_ls[1];
    }
}

extern "C" void kernel_launch(void* const* d_in, const int* in_sizes, int n_in,
                              void* d_out, int out_size)
{
    const float* input  = (const float*)d_in[0];   // (B, S, L) f32
    const int*   label  = (const int*)  d_in[1];   // (B, S) i32
    const int*   length = (const int*)  d_in[2];   // (B,) i32
    const float* trans  = (const float*)d_in[3];   // (L, L) f32
    float* out = (float*)d_out;                    // (B, 1) f32

    const int B = in_sizes[2];
    const int S = in_sizes[1] / B;
    const int nblk = (B + 1) / 2;

    sort_len_kernel<<<1, 1024>>>(length, B, S);
    crf_forward_kernel<<<nblk, 256>>>(input, label, length, trans, out, S, B);
}

// round 6
// speedup vs baseline: 1.6018x; 1.6018x over previous
#include <cuda_runtime.h>
#include <math.h>
#include <limits.h>

// CRF loss: out[b] = logZ(b) - label_score(b).  B=512, S=512, L=128.
//
// Scaled linear-space forward recursion. One block of 128 threads handles
// TWO length-paired batches (rank bid paired with rank B-1-bid from a
// longest-first sort, so every block's total work is ~equal -> one
// balanced wave at 2 CTA/SM). Thread j holds the full column j of
// E=exp(trans) as 64 f32x2 registers and runs BOTH batches' GEMVs as
// interleaved FMA chains (8 independent accumulators). Loop A updates
// both batches; loop B (t >= len_short) only the longer one. U is
// double-buffered in shared, ONE __syncthreads per step; rcp/exp/log are
// off the FFMA chain; log bookkeeping rotates across warps.

#define LDIM 128

__device__ int d_perm[1024];

__device__ __forceinline__ unsigned long long pack_f32x2(float lo, float hi) {
    unsigned long long r;
    asm("mov.b64 %0, {%1, %2};" : "=l"(r) : "f"(lo), "f"(hi));
    return r;
}
__device__ __forceinline__ void unpack_f32x2(unsigned long long v, float& lo, float& hi) {
    asm("mov.b64 {%0, %1}, %2;" : "=f"(lo), "=f"(hi) : "l"(v));
}
__device__ __forceinline__ unsigned long long fma_f32x2(unsigned long long a,
                                                        unsigned long long b,
                                                        unsigned long long c) {
    unsigned long long d;
    asm("fma.rn.f32x2 %0, %1, %2, %3;" : "=l"(d) : "l"(a), "l"(b), "l"(c));
    return d;
}
__device__ __forceinline__ unsigned long long add_f32x2(unsigned long long a,
                                                        unsigned long long b) {
    unsigned long long d;
    asm("add.rn.f32x2 %0, %1, %2;" : "=l"(d) : "l"(a), "l"(b));
    return d;
}
__device__ __forceinline__ float rcp_approx(float x) {
    float r;
    asm("rcp.approx.ftz.f32 %0, %1;" : "=f"(r) : "f"(x));
    return r;
}

// ------------- longest-first permutation (bitonic, 1 block) ---------------
__global__ void sort_len_kernel(const int* __restrict__ length, int B, int S)
{
    __shared__ int key[1024];
    __shared__ int val[1024];
    const int t = threadIdx.x;

    int k = INT_MAX;
    if (t < B) {
        int L = length[t];
        L = L < 1 ? 1 : (L > S ? S : L);
        k = -L;               // ascending on -len => longest first
    }
    key[t] = k;
    val[t] = t;
    __syncthreads();

    for (int kk = 2; kk <= 1024; kk <<= 1) {
        for (int s = kk >> 1; s > 0; s >>= 1) {
            int p = t ^ s;
            if (p > t) {
                bool up = ((t & kk) == 0);
                int kt = key[t], kp = key[p];
                if ((kt > kp) == up) {
                    key[t] = kp; key[p] = kt;
                    int vt = val[t]; val[t] = val[p]; val[p] = vt;
                }
            }
            __syncthreads();
        }
    }
    if (t < B) d_perm[t] = val[t];
}

// ------------------------------ main kernel --------------------------------
__global__ __launch_bounds__(128, 2)
void crf_forward_kernel(const float* __restrict__ input,
                        const int*   __restrict__ label,
                        const int*   __restrict__ length,
                        const float* __restrict__ trans,
                        float* __restrict__ out,
                        int S, int B)
{
    __shared__ __align__(16) float u_sh[2][2][LDIM];   // [buf][g][state]
    __shared__ float wred[2][4];
    __shared__ float wlog[2][4];
    __shared__ float s_x00[2];
    __shared__ float s_ls[2];

    const int tid = threadIdx.x;      // == state column j
    const int j   = tid;
    const int w   = tid >> 5;
    const int l   = tid & 31;

    const int bid = blockIdx.x;
    const int b0  = d_perm[bid];          // longer of the pair
    const int b1  = d_perm[B - 1 - bid];  // shorter (or same if middle)

    int len0 = length[b0]; len0 = len0 < 1 ? 1 : (len0 > S ? S : len0);
    int len1 = length[b1]; len1 = len1 < 1 ? 1 : (len1 > S ? S : len1);
    if (len1 > len0) { int tmp = len0; len0 = len1; len1 = tmp;
                       /* keep b mapping: swap handled by symmetric code */ }
    // note: sort guarantees len(b0) >= len(b1) for bid < B-1-bid, so the
    // swap above only fires for the degenerate middle block (b0==b1).

    const float* xb0 = input + (size_t)b0 * S * LDIM;
    const float* xb1 = input + (size_t)b1 * S * LDIM;

    // ---------------- label scores (both batches) ----------------------
    #pragma unroll
    for (int g = 0; g < 2; g++) {
        const float* xb = g ? xb1 : xb0;
        const int* labb = label + (size_t)(g ? b1 : b0) * S;
        const int  len  = g ? len1 : len0;
        float ls = 0.f;
        for (int t = tid; t < len; t += LDIM) {
            int lab = labb[t];
            ls += xb[(size_t)t * LDIM + lab];
            if (t + 1 < len) ls += trans[lab * LDIM + labb[t + 1]];
        }
        #pragma unroll
        for (int o = 16; o > 0; o >>= 1)
            ls += __shfl_xor_sync(0xffffffffu, ls, o);
        if (l == 0) wred[g][w] = ls;
    }
    __syncthreads();
    if (tid < 2)
        s_ls[tid] = (wred[tid][0] + wred[tid][1]) + (wred[tid][2] + wred[tid][3]);

    // -------- full column j of E: 64 f32x2 registers -------------------
    unsigned long long E2[64];
    #pragma unroll
    for (int k = 0; k < 64; k++) {
        float lo = __expf(trans[(2 * k)     * LDIM + j]);
        float hi = __expf(trans[(2 * k + 1) * LDIM + j]);
        E2[k] = pack_f32x2(lo, hi);
    }

    // ---------------- init U and prefetch pipeline ----------------------
    float x0_0 = xb0[j];
    float x0_1 = xb1[j];
    if (tid == 0) { s_x00[0] = x0_0; s_x00[1] = x0_1; }   // j==0 values
    __syncthreads();
    const float X00 = s_x00[0];
    const float X01 = s_x00[1];
    float U0 = __expf(x0_0 - X00);
    float U1 = __expf(x0_1 - X01);
    u_sh[0][0][j] = U0;
    u_sh[0][1][j] = U1;

    const float* xend0 = xb0 + (size_t)(len0 - 1) * LDIM + j;
    const float* xend1 = xb1 + (size_t)(len1 - 1) * LDIM + j;
    const float* xp0 = xb0 + j + LDIM; if (xp0 > xend0) xp0 = xend0;
    const float* xp1 = xb1 + j + LDIM; if (xp1 > xend1) xp1 = xend1;
    float xA0 = *xp0, xA1 = *xp1;                  // x for t=1
    xp0 += LDIM; if (xp0 > xend0) xp0 = xend0;
    xp1 += LDIM; if (xp1 > xend1) xp1 = xend1;
    float xB0 = *xp0, xB1 = *xp1;                  // x for t=2

    float alog0 = 0.f, alog1 = 0.f;                // rotating owners only
    __syncthreads();

    int cur = 0;
    int t = 1;

    // ---------------- loop A: both batches active (t < len1) ------------
    for (; t < len1; t++) {
        const int nxt = cur ^ 1;
        const float r0  = rcp_approx(u_sh[cur][0][0]);
        const float r1  = rcp_approx(u_sh[cur][1][0]);
        const float ex0 = __expf(xA0);
        const float ex1 = __expf(xA1);

        xA0 = xB0; xA1 = xB1;
        xp0 += LDIM; if (xp0 > xend0) xp0 = xend0;
        xp1 += LDIM; if (xp1 > xend1) xp1 = xend1;
        xB0 = *xp0; xB1 = *xp1;

        const ulonglong2* p0 = (const ulonglong2*)u_sh[cur][0];
        const ulonglong2* p1 = (const ulonglong2*)u_sh[cur][1];
        unsigned long long a0 = 0ull, a1 = 0ull, a2 = 0ull, a3 = 0ull;
        unsigned long long c0 = 0ull, c1 = 0ull, c2 = 0ull, c3 = 0ull;
        #pragma unroll
        for (int k = 0; k < 32; k += 2) {
            ulonglong2 ua = p0[k];
            ulonglong2 ub = p0[k + 1];
            ulonglong2 va = p1[k];
            ulonglong2 vb = p1[k + 1];
            a0 = fma_f32x2(ua.x, E2[2 * k + 0], a0);
            a1 = fma_f32x2(ua.y, E2[2 * k + 1], a1);
            c0 = fma_f32x2(va.x, E2[2 * k + 0], c0);
            c1 = fma_f32x2(va.y, E2[2 * k + 1], c1);
            a2 = fma_f32x2(ub.x, E2[2 * k + 2], a2);
            a3 = fma_f32x2(ub.y, E2[2 * k + 3], a3);
            c2 = fma_f32x2(vb.x, E2[2 * k + 2], c2);
            c3 = fma_f32x2(vb.y, E2[2 * k + 3], c3);
        }
        unsigned long long sa = add_f32x2(add_f32x2(a0, a1), add_f32x2(a2, a3));
        unsigned long long sc = add_f32x2(add_f32x2(c0, c1), add_f32x2(c2, c3));
        float sa_lo, sa_hi, sc_lo, sc_hi;
        unpack_f32x2(sa, sa_lo, sa_hi);
        unpack_f32x2(sc, sc_lo, sc_hi);

        U0 = (sa_lo + sa_hi) * (r0 * ex0);
        U1 = (sc_lo + sc_hi) * (r1 * ex1);
        u_sh[nxt][0][j] = U0;
        u_sh[nxt][1][j] = U1;
        if (tid == ((t & 3) << 5)) {               // rotate MUFU log owner
            alog0 += __logf(r0);
            alog1 += __logf(r1);
        }
        cur = nxt;
        __syncthreads();
    }

    // ---------------- loop B: only batch 0 active (len1 <= t < len0) ----
    for (; t < len0; t++) {
        const int nxt = cur ^ 1;
        const float r0  = rcp_approx(u_sh[cur][0][0]);
        const float ex0 = __expf(xA0);

        xA0 = xB0;
        xp0 += LDIM; if (xp0 > xend0) xp0 = xend0;
        xB0 = *xp0;

        const ulonglong2* p0 = (const ulonglong2*)u_sh[cur][0];
        unsigned long long a0 = 0ull, a1 = 0ull, a2 = 0ull, a3 = 0ull;
        #pragma unroll
        for (int k = 0; k < 32; k += 2) {
            ulonglong2 ua = p0[k];
            ulonglong2 ub = p0[k + 1];
            a0 = fma_f32x2(ua.x, E2[2 * k + 0], a0);
            a1 = fma_f32x2(ua.y, E2[2 * k + 1], a1);
            a2 = fma_f32x2(ub.x, E2[2 * k + 2], a2);
            a3 = fma_f32x2(ub.y, E2[2 * k + 3], a3);
        }
        unsigned long long sa = add_f32x2(add_f32x2(a0, a1), add_f32x2(a2, a3));
        float sa_lo, sa_hi;
        unpack_f32x2(sa, sa_lo, sa_hi);

        U0 = (sa_lo + sa_hi) * (r0 * ex0);
        u_sh[nxt][0][j] = U0;
        if (tid == ((t & 3) << 5))
            alog0 += __logf(r0);
        cur = nxt;
        __syncthreads();
    }

    // ---------------- outputs ------------------------------------------
    float es0 = U0, es1 = U1;
    #pragma unroll
    for (int o = 16; o > 0; o >>= 1) {
        es0 += __shfl_xor_sync(0xffffffffu, es0, o);
        es1 += __shfl_xor_sync(0xffffffffu, es1, o);
    }
    if (l == 0) {
        wred[0][w] = es0;
        wred[1][w] = es1;
        wlog[0][w] = alog0;   // only lane-0 threads ever accumulated
        wlog[1][w] = alog1;
    }
    __syncthreads();
    if (tid == 0) {
        float ss0 = (wred[0][0] + wred[0][1]) + (wred[0][2] + wred[0][3]);
        float ss1 = (wred[1][0] + wred[1][1]) + (wred[1][2] + wred[1][3]);
        float al0 = (wlog[0][0] + wlog[0][1]) + (wlog[0][2] + wlog[0][3]);
        float al1 = (wlog[1][0] + wlog[1][1]) + (wlog[1][2] + wlog[1][3]);
        out[b0] = X00 - al0 + logf(ss0) - s_ls[0];
        out[b1] = X01 - al1 + logf(ss1) - s_ls[1];
    }
}

extern "C" void kernel_launch(void* const* d_in, const int* in_sizes, int n_in,
                              void* d_out, int out_size)
{
    const float* input  = (const float*)d_in[0];   // (B, S, L) f32
    const int*   label  = (const int*)  d_in[1];   // (B, S) i32
    const int*   length = (const int*)  d_in[2];   // (B,) i32
    const float* trans  = (const float*)d_in[3];   // (L, L) f32
    float* out = (float*)d_out;                    // (B, 1) f32

    const int B = in_sizes[2];
    const int S = in_sizes[1] / B;
    const int nblk = (B + 1) / 2;

    sort_len_kernel<<<1, 1024>>>(length, B, S);
    crf_forward_kernel<<<nblk, 128>>>(input, label, length, trans, out, S, B);
}